// round 17
// baseline (speedup 1.0000x reference)
#include <cuda_runtime.h>
#include <cuda_bf16.h>
#include <stdint.h>

#define NN 100000
#define NE 1600000
#define SCAN_B 1024
#define NB ((NN + SCAN_B - 1) / SCAN_B)   // 98

// global B: unpadded 64 u32 per k-row; smem: padded 68 u32 rows (LDSM conflict-free)
#define BGU 64
#define BSU 68
#define BCH4 256   // uint4 per 16-row B chunk (16*64/4) == blockDim

// dynamic smem layout (bytes)
#define SM_AGG   0
#define SM_AHU   67584
#define SM_ALU   (67584 + 6144)
#define SM_BSH   (67584 + 12288)
#define SM_BSL   (67584 + 12288 + 4352)
#define SM_TOTAL (67584 + 12288 + 8704)   // 88576

// ---------------- scratch (device globals) ---------------------------------
__device__ int   g_is64;
__device__ int   g_cnt[NN];
__device__ int   g_rptr[NN + 1];
__device__ int   g_woff[NN];
__device__ int   g_bsum[NB];
__device__ int   g_col[NE];
__device__ __align__(16) float    g_z1[NN * 64];
__device__ __align__(16) float    g_r1[NN * 64];
__device__ __align__(16) uint32_t g_B1h[256 * BGU];
__device__ __align__(16) uint32_t g_B1l[256 * BGU];
__device__ __align__(16) uint32_t g_B2h[128 * BGU];
__device__ __align__(16) uint32_t g_B2l[128 * BGU];

// ---------------- helpers --------------------------------------------------
__device__ __forceinline__ uint32_t sptr(const void* p) {
    uint32_t a;
    asm("{ .reg .u64 t; cvta.to.shared.u64 t, %1; cvt.u32.u64 %0, t; }"
        : "=r"(a) : "l"(p));
    return a;
}

#define LDSM_X4(r0,r1,r2,r3,addr) \
    asm volatile("ldmatrix.sync.aligned.m8n8.x4.shared.b16 {%0,%1,%2,%3}, [%4];" \
        : "=r"(r0),"=r"(r1),"=r"(r2),"=r"(r3) : "r"(addr))

#define LDSM_X4_T(r0,r1,r2,r3,addr) \
    asm volatile("ldmatrix.sync.aligned.m8n8.x4.trans.shared.b16 {%0,%1,%2,%3}, [%4];" \
        : "=r"(r0),"=r"(r1),"=r"(r2),"=r"(r3) : "r"(addr))

#define MMA16816(c, a0,a1,a2,a3, b0,b1) \
    asm volatile("mma.sync.aligned.m16n8k16.row.col.f32.bf16.bf16.f32 " \
        "{%0,%1,%2,%3},{%4,%5,%6,%7},{%8,%9},{%0,%1,%2,%3};" \
        : "+f"((c)[0]),"+f"((c)[1]),"+f"((c)[2]),"+f"((c)[3]) \
        : "r"(a0),"r"(a1),"r"(a2),"r"(a3),"r"(b0),"r"(b1))

__device__ __forceinline__ void split2(float f0, float f1, uint32_t& hi, uint32_t& lo) {
    __nv_bfloat162 h, l;
    h.x = __float2bfloat16(f0);
    h.y = __float2bfloat16(f1);
    l.x = __float2bfloat16(f0 - __bfloat162float(h.x));
    l.y = __float2bfloat16(f1 - __bfloat162float(h.y));
    hi = *reinterpret_cast<uint32_t*>(&h);
    lo = *reinterpret_cast<uint32_t*>(&l);
}

__device__ __forceinline__ int edge_at(const void* ei, int idx) {
    return g_is64 ? (int)((const long long*)ei)[idx] : ((const int*)ei)[idx];
}

// ---------------- CSR build ----------------
__global__ void k_zero(const int* __restrict__ ei32, int n) {
    int i = blockIdx.x * blockDim.x + threadIdx.x;
    if (i < n) g_cnt[i] = 0;
    if (blockIdx.x == 0) {
        __shared__ int nz;
        if (threadIdx.x == 0) nz = 0;
        __syncthreads();
        int v = 0;
        for (int j = threadIdx.x; j < 1024; j += 256) v |= ei32[2 * j + 1];
        if (v) atomicOr(&nz, 1);
        __syncthreads();
        if (threadIdx.x == 0) g_is64 = (nz == 0) ? 1 : 0;
    }
}

__global__ void k_hist(const void* __restrict__ ei, int E) {
    int e = blockIdx.x * blockDim.x + threadIdx.x;
    if (e < E) {
        int d = edge_at(ei, E + e);
        if ((unsigned)d < (unsigned)NN) atomicAdd(&g_cnt[d], 1);
    }
}

__global__ void k_scan_blocks(int n) {
    __shared__ int wsum[32];
    int tid  = threadIdx.x;
    int lane = tid & 31, wid = tid >> 5;
    int i = blockIdx.x * SCAN_B + tid;
    int v = (i < n) ? g_cnt[i] : 0;
    int x = v;
    #pragma unroll
    for (int d = 1; d < 32; d <<= 1) {
        int t = __shfl_up_sync(0xffffffffu, x, d);
        if (lane >= d) x += t;
    }
    if (lane == 31) wsum[wid] = x;
    __syncthreads();
    if (wid == 0) {
        int s = wsum[lane];
        #pragma unroll
        for (int d = 1; d < 32; d <<= 1) {
            int t = __shfl_up_sync(0xffffffffu, s, d);
            if (lane >= d) s += t;
        }
        wsum[lane] = s;
    }
    __syncthreads();
    int woffs = (wid > 0) ? wsum[wid - 1] : 0;
    if (i < n) g_rptr[i] = woffs + x - v;
    if (tid == SCAN_B - 1) g_bsum[blockIdx.x] = wsum[31];
}

__global__ void k_add_off(int n, int E, int nb) {
    __shared__ int pre[NB];
    int tid = threadIdx.x;
    if (tid < nb) pre[tid] = g_bsum[tid];
    __syncthreads();
    if (tid == 0) {
        int a = 0;
        for (int i = 0; i < nb; i++) { int t = pre[i]; pre[i] = a; a += t; }
    }
    __syncthreads();
    int i = blockIdx.x * SCAN_B + tid;
    if (i < n) {
        int v = g_rptr[i] + pre[blockIdx.x];
        g_rptr[i] = v;
        g_woff[i] = v;
    }
    if (i == 0) g_rptr[n] = E;
}

__global__ void k_scatter(const void* __restrict__ ei, int E) {
    int e = blockIdx.x * blockDim.x + threadIdx.x;
    if (e < E) {
        int s = edge_at(ei, e);
        int d = edge_at(ei, E + e);
        if ((unsigned)s < (unsigned)NN && (unsigned)d < (unsigned)NN) {
            int p = atomicAdd(&g_woff[d], 1);
            if ((unsigned)p < (unsigned)NE) g_col[p] = s;
        }
    }
}

// ---------------- weight packing: fp32 -> bf16 hi/lo, UNPADDED rows --------
__global__ void k_pack(const float* __restrict__ Wl0, const float* __restrict__ Wr0,
                       const float* __restrict__ Wl1, const float* __restrict__ Wr1) {
    int i = blockIdx.x * blockDim.x + threadIdx.x;
    if (i < 256 * BGU) {
        int k = i >> 6, c = i & 63;
        const float* W = (k < 128) ? Wl0 : Wr0;
        int kk = k & 127;
        float f0 = W[kk * 128 + 2 * c];
        float f1 = W[kk * 128 + 2 * c + 1];
        uint32_t hi, lo;
        split2(f0, f1, hi, lo);
        g_B1h[i] = hi; g_B1l[i] = lo;
    }
    if (i < 128 * BGU) {
        int k = i >> 6, c = i & 63;
        float f0, f1;
        if (c < 32) {
            f0 = Wl1[k * 64 + 2 * c];
            f1 = Wl1[k * 64 + 2 * c + 1];
        } else {
            int cc = c - 32;
            f0 = Wr1[k * 64 + 2 * cc];
            f1 = Wr1[k * 64 + 2 * cc + 1];
        }
        uint32_t hi, lo;
        split2(f0, f1, hi, lo);
        g_B2h[i] = hi; g_B2l[i] = lo;
    }
}

// ---------------- mega kernel: 128-row tile, 256 threads -------------------
// Each warp owns TWO 16-row bands (acc[2][8][4]); B restream amortized over
// 128 output rows (half the L2 weight traffic of the 64-row tile).
__global__ void __launch_bounds__(256, 2) k_layer1(
    const float* __restrict__ x,
    const float* __restrict__ bias,
    int M)
{
    extern __shared__ __align__(16) char dynsmem[];
    float (*Agg)[132] = (float(*)[132])(dynsmem + SM_AGG);
    uint32_t* Ahu = (uint32_t*)(dynsmem + SM_AHU);
    uint32_t* Alu = (uint32_t*)(dynsmem + SM_ALU);
    uint32_t* BsH = (uint32_t*)(dynsmem + SM_BSH);
    uint32_t* BsL = (uint32_t*)(dynsmem + SM_BSL);

    int tid  = threadIdx.x;
    int lane = tid & 31, w = tid >> 5;
    int tile0 = blockIdx.x * 128;

    // -------- Phase A: gather-mean of x into Agg (16 rows per warp) --------
    #pragma unroll 1
    for (int u = 0; u < 16; u++) {
        int r = w * 16 + u;
        int node = tile0 + r;
        float4 acc4 = make_float4(0.f, 0.f, 0.f, 0.f);
        if (node < M) {
            int rs = g_rptr[node], re = g_rptr[node + 1];
            int j = rs;
            for (; j + 4 <= re; j += 4) {
                int s0 = g_col[j], s1 = g_col[j+1], s2 = g_col[j+2], s3 = g_col[j+3];
                float4 v0 = *(const float4*)&x[s0 * 128 + lane * 4];
                float4 v1 = *(const float4*)&x[s1 * 128 + lane * 4];
                float4 v2 = *(const float4*)&x[s2 * 128 + lane * 4];
                float4 v3 = *(const float4*)&x[s3 * 128 + lane * 4];
                acc4.x += v0.x + v1.x + v2.x + v3.x;
                acc4.y += v0.y + v1.y + v2.y + v3.y;
                acc4.z += v0.z + v1.z + v2.z + v3.z;
                acc4.w += v0.w + v1.w + v2.w + v3.w;
            }
            for (; j < re; j++) {
                int s = g_col[j];
                float4 v = *(const float4*)&x[s * 128 + lane * 4];
                acc4.x += v.x; acc4.y += v.y; acc4.z += v.z; acc4.w += v.w;
            }
            int deg = re - rs;
            float inv = 1.0f / (float)(deg > 1 ? deg : 1);
            acc4.x *= inv; acc4.y *= inv; acc4.z *= inv; acc4.w *= inv;
        }
        *(float4*)&Agg[r][lane * 4] = acc4;
    }

    // -------- per-warp MMA geometry --------
    int wr = (w & 3) * 32;          // 32-row band (two 16-row sub-bands)
    int wc = (w >> 2) * 64;         // column half

    uint32_t aAddrH0 = sptr(Ahu) + (wr + (lane & 15)) * 48 + ((lane >> 4) << 4);
    uint32_t aAddrL0 = sptr(Alu) + (wr + (lane & 15)) * 48 + ((lane >> 4) << 4);
    uint32_t aAddrH1 = aAddrH0 + 16 * 48;
    uint32_t aAddrL1 = aAddrL0 + 16 * 48;
    uint32_t bBase  = (lane & 15) * (BSU * 4) + (wc + ((lane >> 4) << 3)) * 2;
    uint32_t bAddrH = sptr(BsH) + bBase;
    uint32_t bAddrL = sptr(BsL) + bBase;

    // A staging: 2 threads per row, 8 floats each
    int arow = tid >> 1;
    int ak8  = (tid & 1) * 8;
    int acol = arow * 12 + (tid & 1) * 4;

    // B staging: thread -> one uint4 of the 16x64-u32 chunk
    int brow = tid >> 4, bc4 = tid & 15;
    uint32_t bsOff = brow * BSU + bc4 * 4;

    int r0   = wr + (lane >> 2);
    int col0 = wc + (lane & 3) * 2;

    // prefetch registers
    uint4 pbH, pbL;
    float4 aPreA = make_float4(0.f, 0.f, 0.f, 0.f), aPreB = aPreA;

    // prologue: prefetch B1 chunk 0
    {
        const uint4* s4h = (const uint4*)(g_B1h);
        const uint4* s4l = (const uint4*)(g_B1l);
        pbH = s4h[tid]; pbL = s4l[tid];
    }
    __syncthreads();   // gather complete

    // -------- Phase B: GEMM1 [Agg | x] (K=256) @ B1 --------
    float acc[2][8][4];
    #pragma unroll
    for (int b = 0; b < 2; b++)
        #pragma unroll
        for (int t = 0; t < 8; t++) {
            acc[b][t][0] = 0.f; acc[b][t][1] = 0.f;
            acc[b][t][2] = 0.f; acc[b][t][3] = 0.f;
        }

    #pragma unroll 1
    for (int c = 0; c < 16; c++) {
        int kc = c * 16;
        *(uint4*)&BsH[bsOff] = pbH;
        *(uint4*)&BsL[bsOff] = pbL;
        {
            float4 v0, v1;
            if (kc < 128) {
                v0 = *(const float4*)&Agg[arow][kc + ak8];
                v1 = *(const float4*)&Agg[arow][kc + ak8 + 4];
            } else {
                v0 = aPreA; v1 = aPreB;
            }
            uint32_t h0, l0, h1, l1, h2, l2, h3, l3;
            split2(v0.x, v0.y, h0, l0);
            split2(v0.z, v0.w, h1, l1);
            split2(v1.x, v1.y, h2, l2);
            split2(v1.z, v1.w, h3, l3);
            Ahu[acol] = h0; Ahu[acol + 1] = h1; Ahu[acol + 2] = h2; Ahu[acol + 3] = h3;
            Alu[acol] = l0; Alu[acol + 1] = l1; Alu[acol + 2] = l2; Alu[acol + 3] = l3;
        }
        __syncthreads();
        if (c < 15) {
            int nk = kc + 16;
            const uint4* s4h = (const uint4*)(g_B1h + nk * BGU);
            const uint4* s4l = (const uint4*)(g_B1l + nk * BGU);
            pbH = s4h[tid]; pbL = s4l[tid];
            if (nk >= 128) {
                int gr = tile0 + arow;
                aPreA = make_float4(0.f, 0.f, 0.f, 0.f); aPreB = aPreA;
                if (gr < M) {
                    aPreA = *(const float4*)&x[gr * 128 + (nk - 128) + ak8];
                    aPreB = *(const float4*)&x[gr * 128 + (nk - 128) + ak8 + 4];
                }
            }
        }

        uint32_t ah[2][4], al[2][4];
        LDSM_X4(ah[0][0], ah[0][1], ah[0][2], ah[0][3], aAddrH0);
        LDSM_X4(al[0][0], al[0][1], al[0][2], al[0][3], aAddrL0);
        LDSM_X4(ah[1][0], ah[1][1], ah[1][2], ah[1][3], aAddrH1);
        LDSM_X4(al[1][0], al[1][1], al[1][2], al[1][3], aAddrL1);

        #pragma unroll
        for (int p = 0; p < 4; p++) {
            uint32_t bh0, bh1, bh2, bh3, bl0, bl1, bl2, bl3;
            LDSM_X4_T(bh0, bh1, bh2, bh3, bAddrH + p * 32);
            LDSM_X4_T(bl0, bl1, bl2, bl3, bAddrL + p * 32);
            #pragma unroll
            for (int b = 0; b < 2; b++) {
                MMA16816(acc[b][2*p],   ah[b][0], ah[b][1], ah[b][2], ah[b][3], bh0, bh1);
                MMA16816(acc[b][2*p],   ah[b][0], ah[b][1], ah[b][2], ah[b][3], bl0, bl1);
                MMA16816(acc[b][2*p],   al[b][0], al[b][1], al[b][2], al[b][3], bh0, bh1);
                MMA16816(acc[b][2*p+1], ah[b][0], ah[b][1], ah[b][2], ah[b][3], bh2, bh3);
                MMA16816(acc[b][2*p+1], ah[b][0], ah[b][1], ah[b][2], ah[b][3], bl2, bl3);
                MMA16816(acc[b][2*p+1], al[b][0], al[b][1], al[b][2], al[b][3], bh2, bh3);
            }
        }
        __syncthreads();
    }

    // -------- h = relu(acc + bias) -> Agg (fp32 smem) --------
    #pragma unroll
    for (int b = 0; b < 2; b++) {
        int rb = r0 + b * 16;
        #pragma unroll
        for (int nt = 0; nt < 8; nt++) {
            int col = col0 + nt * 8;
            float b0 = bias[col], b1 = bias[col + 1];
            float2 o;
            o.x = acc[b][nt][0] + b0; o.y = acc[b][nt][1] + b1;
            o.x = o.x > 0.f ? o.x : 0.f;
            o.y = o.y > 0.f ? o.y : 0.f;
            *(float2*)&Agg[rb][col] = o;
            o.x = acc[b][nt][2] + b0; o.y = acc[b][nt][3] + b1;
            o.x = o.x > 0.f ? o.x : 0.f;
            o.y = o.y > 0.f ? o.y : 0.f;
            *(float2*)&Agg[rb + 8][col] = o;
        }
    }

    // reuse acc for GEMM2
    #pragma unroll
    for (int b = 0; b < 2; b++)
        #pragma unroll
        for (int t = 0; t < 8; t++) {
            acc[b][t][0] = 0.f; acc[b][t][1] = 0.f;
            acc[b][t][2] = 0.f; acc[b][t][3] = 0.f;
        }
    {
        const uint4* s4h = (const uint4*)(g_B2h);
        const uint4* s4l = (const uint4*)(g_B2l);
        pbH = s4h[tid]; pbL = s4l[tid];
    }
    __syncthreads();   // h writes visible

    // -------- Phase C: GEMM2 h (K=128, smem) @ B2 -> z1 | r1 ---------------
    #pragma unroll 1
    for (int c = 0; c < 8; c++) {
        int kc = c * 16;
        *(uint4*)&BsH[bsOff] = pbH;
        *(uint4*)&BsL[bsOff] = pbL;
        {
            float4 v0 = *(const float4*)&Agg[arow][kc + ak8];
            float4 v1 = *(const float4*)&Agg[arow][kc + ak8 + 4];
            uint32_t h0, l0, h1, l1, h2, l2, h3, l3;
            split2(v0.x, v0.y, h0, l0);
            split2(v0.z, v0.w, h1, l1);
            split2(v1.x, v1.y, h2, l2);
            split2(v1.z, v1.w, h3, l3);
            Ahu[acol] = h0; Ahu[acol + 1] = h1; Ahu[acol + 2] = h2; Ahu[acol + 3] = h3;
            Alu[acol] = l0; Alu[acol + 1] = l1; Alu[acol + 2] = l2; Alu[acol + 3] = l3;
        }
        __syncthreads();
        if (c < 7) {
            int nk = kc + 16;
            const uint4* s4h = (const uint4*)(g_B2h + nk * BGU);
            const uint4* s4l = (const uint4*)(g_B2l + nk * BGU);
            pbH = s4h[tid]; pbL = s4l[tid];
        }

        uint32_t ah[2][4], al[2][4];
        LDSM_X4(ah[0][0], ah[0][1], ah[0][2], ah[0][3], aAddrH0);
        LDSM_X4(al[0][0], al[0][1], al[0][2], al[0][3], aAddrL0);
        LDSM_X4(ah[1][0], ah[1][1], ah[1][2], ah[1][3], aAddrH1);
        LDSM_X4(al[1][0], al[1][1], al[1][2], al[1][3], aAddrL1);

        #pragma unroll
        for (int p = 0; p < 4; p++) {
            uint32_t bh0, bh1, bh2, bh3, bl0, bl1, bl2, bl3;
            LDSM_X4_T(bh0, bh1, bh2, bh3, bAddrH + p * 32);
            LDSM_X4_T(bl0, bl1, bl2, bl3, bAddrL + p * 32);
            #pragma unroll
            for (int b = 0; b < 2; b++) {
                MMA16816(acc[b][2*p],   ah[b][0], ah[b][1], ah[b][2], ah[b][3], bh0, bh1);
                MMA16816(acc[b][2*p],   ah[b][0], ah[b][1], ah[b][2], ah[b][3], bl0, bl1);
                MMA16816(acc[b][2*p],   al[b][0], al[b][1], al[b][2], al[b][3], bh0, bh1);
                MMA16816(acc[b][2*p+1], ah[b][0], ah[b][1], ah[b][2], ah[b][3], bh2, bh3);
                MMA16816(acc[b][2*p+1], ah[b][0], ah[b][1], ah[b][2], ah[b][3], bl2, bl3);
                MMA16816(acc[b][2*p+1], al[b][0], al[b][1], al[b][2], al[b][3], bh2, bh3);
            }
        }
        __syncthreads();
    }

    // -------- epilogue: z1 | r1 --------
    #pragma unroll
    for (int b = 0; b < 2; b++) {
        int rb = r0 + b * 16;
        int gmA = tile0 + rb, gmB = gmA + 8;
        #pragma unroll
        for (int nt = 0; nt < 8; nt++) {
            int col = col0 + nt * 8;
            float* dst = (col < 64) ? g_z1 : g_r1;
            int cc = col & 63;
            if (gmA < M) {
                float2 o; o.x = acc[b][nt][0]; o.y = acc[b][nt][1];
                *(float2*)&dst[gmA * 64 + cc] = o;
            }
            if (gmB < M) {
                float2 o; o.x = acc[b][nt][2]; o.y = acc[b][nt][3];
                *(float2*)&dst[gmB * 64 + cc] = o;
            }
        }
    }
}

// ---------------- final: out = mean_agg(z1) + bl1 + r1 ---------------------
__global__ void k_out(const float* __restrict__ bias, float* __restrict__ out, int n) {
    int warp = (blockIdx.x * blockDim.x + threadIdx.x) >> 5;
    int lane = threadIdx.x & 31;
    if (warp >= n) return;
    int rs = g_rptr[warp], re = g_rptr[warp + 1];
    int d0 = lane * 2;
    float2 acc = make_float2(0.f, 0.f);
    int j = rs;
    for (; j + 4 <= re; j += 4) {
        int s0 = g_col[j], s1 = g_col[j + 1], s2 = g_col[j + 2], s3 = g_col[j + 3];
        float2 v0 = *(const float2*)&g_z1[s0 * 64 + d0];
        float2 v1 = *(const float2*)&g_z1[s1 * 64 + d0];
        float2 v2 = *(const float2*)&g_z1[s2 * 64 + d0];
        float2 v3 = *(const float2*)&g_z1[s3 * 64 + d0];
        acc.x += v0.x + v1.x + v2.x + v3.x;
        acc.y += v0.y + v1.y + v2.y + v3.y;
    }
    for (; j < re; j++) {
        int s = g_col[j];
        float2 v = *(const float2*)&g_z1[s * 64 + d0];
        acc.x += v.x; acc.y += v.y;
    }
    int deg = re - rs;
    float inv = 1.0f / (float)(deg > 1 ? deg : 1);
    float2 r = *(const float2*)&g_r1[warp * 64 + d0];
    float2 o;
    o.x = acc.x * inv + bias[d0]     + r.x;
    o.y = acc.y * inv + bias[d0 + 1] + r.y;
    *(float2*)&out[warp * 64 + d0] = o;
}

// ---------------- launch ----------------------------------------------------
extern "C" void kernel_launch(void* const* d_in, const int* in_sizes, int n_in,
                              void* d_out, int out_size) {
    const float* x   = (const float*)d_in[0];
    const void*  ei  = d_in[1];
    const float* Wl0 = (const float*)d_in[2];
    const float* bl0 = (const float*)d_in[3];
    const float* Wr0 = (const float*)d_in[4];
    const float* Wl1 = (const float*)d_in[5];
    const float* bl1 = (const float*)d_in[6];
    const float* Wr1 = (const float*)d_in[7];
    float* out = (float*)d_out;

    int M = in_sizes[0] / 128;      // 100000
    int E = in_sizes[1] / 2;        // 1600000

    // idempotent, not a stream op — capture-safe
    cudaFuncSetAttribute(k_layer1, cudaFuncAttributeMaxDynamicSharedMemorySize, SM_TOTAL);

    k_zero<<<(M + 255) / 256, 256>>>((const int*)ei, M);
    k_hist<<<(E + 255) / 256, 256>>>(ei, E);
    k_scan_blocks<<<NB, SCAN_B>>>(M);
    k_add_off<<<NB, SCAN_B>>>(M, E, NB);
    k_scatter<<<(E + 255) / 256, 256>>>(ei, E);
    k_pack<<<(256 * BGU + 255) / 256, 256>>>(Wl0, Wr0, Wl1, Wr1);

    int tiles = (M + 127) / 128;
    k_layer1<<<tiles, 256, SM_TOTAL>>>(x, bl0, M);
    k_out<<<(M + 7) / 8, 256>>>(bl1, out, M);
}